// round 14
// baseline (speedup 1.0000x reference)
#include <cuda_runtime.h>
#include <cuda_fp16.h>
#include <cstdint>
#include <math.h>

#define BB 4
#define TTOT 4096
#define CC 2048
#define NH 32
#define HS 64
#define ROWS (BB*TTOT)
#define ELEMS ((size_t)ROWS*(size_t)CC)
#define NCHUNK 64
#define TCH (TTOT/NCHUNK)      // 64

typedef __half f16;

#define BM 128
#define BN 128
#define BKT 32
#define TILE_B (128*80)
#define STAGE_B (2*TILE_B)
#define NSTG 4
#define SMEM_B (NSTG*STAGE_B)
#define KTILES (CC/BKT)

// ---------------------------------------------------------------------------
// Scratch
// ---------------------------------------------------------------------------
__device__ f16 g_xr[ELEMS];
__device__ f16 g_xk[ELEMS];
__device__ f16 g_xv[ELEMS];
__device__ f16 g_xg[ELEMS];
__device__ f16 g_y[ELEMS];
__device__ float g_r[ELEMS];
__device__ float g_k[ELEMS];
__device__ float g_v[ELEMS];
__device__ float g_g[ELEMS];
__device__ float g_ao[ELEMS];
__device__ f16 g_WrT[CC*CC];
__device__ f16 g_WkT[CC*CC];
__device__ f16 g_WvT[CC*CC];
__device__ f16 g_WgT[CC*CC];
__device__ f16 g_WoT[CC*CC];
__device__ float g_Sc[(size_t)NCHUNK*128*HS*HS];
__device__ float g_S0c[(size_t)NCHUNK*128*HS*HS];

// ---------------------------------------------------------------------------
// helpers
// ---------------------------------------------------------------------------
__device__ __forceinline__ uint32_t smem_u32(const void* p) {
    uint32_t a;
    asm("{ .reg .u64 t; cvta.to.shared.u64 t, %1; cvt.u32.u64 %0, t; }" : "=r"(a) : "l"(p));
    return a;
}
__device__ __forceinline__ void cpa16(uint32_t dst, const void* src) {
    asm volatile("cp.async.cg.shared.global [%0], [%1], 16;" :: "r"(dst), "l"(src));
}
__device__ __forceinline__ void cp_commit() {
    asm volatile("cp.async.commit_group;" ::: "memory");
}
template<int N> __device__ __forceinline__ void cp_wait() {
    asm volatile("cp.async.wait_group %0;" :: "n"(N) : "memory");
}
__device__ __forceinline__ void ldsm4(uint32_t (&r)[4], uint32_t addr) {
    asm volatile("ldmatrix.sync.aligned.m8n8.x4.shared.b16 {%0,%1,%2,%3}, [%4];"
                 : "=r"(r[0]), "=r"(r[1]), "=r"(r[2]), "=r"(r[3]) : "r"(addr));
}
__device__ __forceinline__ void mma_f16(float (&c)[4], const uint32_t (&a)[4],
                                        uint32_t b0, uint32_t b1) {
    asm volatile(
        "mma.sync.aligned.m16n8k16.row.col.f32.f16.f16.f32 "
        "{%0,%1,%2,%3}, {%4,%5,%6,%7}, {%8,%9}, {%0,%1,%2,%3};"
        : "+f"(c[0]), "+f"(c[1]), "+f"(c[2]), "+f"(c[3])
        : "r"(a[0]), "r"(a[1]), "r"(a[2]), "r"(a[3]), "r"(b0), "r"(b1));
}
__device__ __forceinline__ uint32_t pack_h2(float a, float b) {
    __half2 h = __floats2half2_rn(a, b);
    return *(uint32_t*)&h;
}

// ---------------------------------------------------------------------------
// 1) Token-shift mixing -> fp16 planes
// ---------------------------------------------------------------------------
__global__ void mix_kernel(const float* __restrict__ x,
                           const float* __restrict__ tmk, const float* __restrict__ tmv,
                           const float* __restrict__ tmr, const float* __restrict__ tmg,
                           f16* __restrict__ xk, f16* __restrict__ xv,
                           f16* __restrict__ xr, f16* __restrict__ xg) {
    size_t i4 = (size_t)blockIdx.x * blockDim.x + threadIdx.x;
    if (i4 >= ELEMS / 4) return;
    size_t idx = i4 * 4;
    int c = (int)(idx % CC);
    int t = (int)((idx / CC) % TTOT);

    float4 xc = *(const float4*)(x + idx);
    float4 xp = make_float4(0.f, 0.f, 0.f, 0.f);
    if (t != 0) xp = *(const float4*)(x + idx - CC);
    float4 mk = *(const float4*)(tmk + c);
    float4 mv = *(const float4*)(tmv + c);
    float4 mr = *(const float4*)(tmr + c);
    float4 mg = *(const float4*)(tmg + c);

    uint2 o;
    o.x = pack_h2(xc.x * mk.x + xp.x * (1.f - mk.x), xc.y * mk.y + xp.y * (1.f - mk.y));
    o.y = pack_h2(xc.z * mk.z + xp.z * (1.f - mk.z), xc.w * mk.w + xp.w * (1.f - mk.w));
    *(uint2*)(xk + idx) = o;
    o.x = pack_h2(xc.x * mv.x + xp.x * (1.f - mv.x), xc.y * mv.y + xp.y * (1.f - mv.y));
    o.y = pack_h2(xc.z * mv.z + xp.z * (1.f - mv.z), xc.w * mv.w + xp.w * (1.f - mv.w));
    *(uint2*)(xv + idx) = o;
    o.x = pack_h2(xc.x * mr.x + xp.x * (1.f - mr.x), xc.y * mr.y + xp.y * (1.f - mr.y));
    o.y = pack_h2(xc.z * mr.z + xp.z * (1.f - mr.z), xc.w * mr.w + xp.w * (1.f - mr.w));
    *(uint2*)(xr + idx) = o;
    o.x = pack_h2(xc.x * mg.x + xp.x * (1.f - mg.x), xc.y * mg.y + xp.y * (1.f - mg.y));
    o.y = pack_h2(xc.z * mg.z + xp.z * (1.f - mg.z), xc.w * mg.w + xp.w * (1.f - mg.w));
    *(uint2*)(xg + idx) = o;
}

// ---------------------------------------------------------------------------
// 2) Weight prep (batched over grid.z)
// ---------------------------------------------------------------------------
struct WB { const float* W[5]; f16* O[5]; };

__global__ void wprep_b(WB wb) {
    const float* __restrict__ W = wb.W[blockIdx.z];
    f16* __restrict__ WT = wb.O[blockIdx.z];
    __shared__ float t[32][33];
    int n0 = blockIdx.x * 32, k0 = blockIdx.y * 32;
    int tx = threadIdx.x, ty = threadIdx.y;
    #pragma unroll
    for (int r = ty; r < 32; r += 8)
        t[r][tx] = W[(size_t)(k0 + r) * CC + n0 + tx];
    __syncthreads();
    #pragma unroll
    for (int r = ty; r < 32; r += 8)
        WT[(size_t)(n0 + r) * CC + k0 + tx] = __float2half_rn(t[tx][r]);
}

// ---------------------------------------------------------------------------
// 3) Batched fp16 GEMM — R11 schedule (frozen local optimum)
// ---------------------------------------------------------------------------
struct GB {
    const f16* Ap[4]; const f16* Bp[4];
    float* Cp[4]; int act[4];
};

__global__ __launch_bounds__(256, 2) void tc_gemm_b(GB gb) {
    int z = blockIdx.z;
    const f16* __restrict__ A = gb.Ap[z];
    const f16* __restrict__ B = gb.Bp[z];
    float* __restrict__ C = gb.Cp[z];
    int act = gb.act[z];

    extern __shared__ char smem[];
    uint32_t sb = smem_u32(smem);

    int tid = threadIdx.x;
    int lane = tid & 31;
    int wm = (tid >> 5) & 3;
    int wn = tid >> 7;
    int mBase = blockIdx.y * BM;
    int nBase = blockIdx.x * BN;

    uint32_t dA = (uint32_t)((tid >> 2) * 80 + (tid & 3) * 16);
    const f16* pA = A + (size_t)(mBase + (tid >> 2)) * CC + (tid & 3) * 8;
    const f16* pB = B + (size_t)(nBase + (tid >> 2)) * CC + (tid & 3) * 8;

    float acc[2][8][4];
    #pragma unroll
    for (int i = 0; i < 2; i++)
        #pragma unroll
        for (int j = 0; j < 8; j++)
            #pragma unroll
            for (int q = 0; q < 4; q++) acc[i][j][q] = 0.0f;

    #pragma unroll
    for (int s = 0; s < NSTG - 1; s++) {
        uint32_t stb = sb + s * STAGE_B;
        int k0 = s * BKT;
        cpa16(stb + dA,                 pA + k0);
        cpa16(stb + dA + 5120,          pA + 64 * CC + k0);
        cpa16(stb + TILE_B + dA,        pB + k0);
        cpa16(stb + TILE_B + dA + 5120, pB + 64 * CC + k0);
        cp_commit();
    }

    uint32_t aRow = (uint32_t)(wm * 32 + ((lane >> 3) & 1) * 8 + (lane & 7));
    uint32_t aCol = (uint32_t)((lane >> 4) * 16);
    uint32_t bRow = (uint32_t)(wn * 64 + (lane >> 4) * 8 + (lane & 7));
    uint32_t bCol = (uint32_t)(((lane >> 3) & 1) * 16);
    int ksSkew = wm & 1;

    for (int kt = 0; kt < KTILES; kt++) {
        cp_wait<NSTG - 2>();
        __syncthreads();

        int nt = kt + NSTG - 1;
        if (nt < KTILES) {
            uint32_t stb = sb + (nt & (NSTG - 1)) * STAGE_B;
            int k0 = nt * BKT;
            cpa16(stb + dA,                 pA + k0);
            cpa16(stb + dA + 5120,          pA + 64 * CC + k0);
            cpa16(stb + TILE_B + dA,        pB + k0);
            cpa16(stb + TILE_B + dA + 5120, pB + 64 * CC + k0);
        }
        cp_commit();

        uint32_t stg = sb + (kt & (NSTG - 1)) * STAGE_B;

        #pragma unroll
        for (int kss = 0; kss < 2; kss++) {
            int ks = kss ^ ksSkew;
            uint32_t a_f[2][4];
            #pragma unroll
            for (int mi = 0; mi < 2; mi++) {
                uint32_t ra = (aRow + mi * 16) * 80 + aCol + ks * 32;
                ldsm4(a_f[mi], stg + ra);
            }
            #pragma unroll
            for (int bp = 0; bp < 2; bp++) {
                uint32_t b0[4], b1[4];
                {
                    uint32_t rb0 = (bRow + (2*bp + 0) * 16) * 80 + bCol + ks * 32;
                    uint32_t rb1 = (bRow + (2*bp + 1) * 16) * 80 + bCol + ks * 32;
                    ldsm4(b0, stg + TILE_B + rb0);
                    ldsm4(b1, stg + TILE_B + rb1);
                }
                #pragma unroll
                for (int mi = 0; mi < 2; mi++) {
                    mma_f16(acc[mi][4*bp + 0], a_f[mi], b0[0], b0[1]);
                    mma_f16(acc[mi][4*bp + 1], a_f[mi], b0[2], b0[3]);
                    mma_f16(acc[mi][4*bp + 2], a_f[mi], b1[0], b1[1]);
                    mma_f16(acc[mi][4*bp + 3], a_f[mi], b1[2], b1[3]);
                }
            }
        }
    }

    int mrow = mBase + wm * 32 + (lane >> 2);
    int ncolbase = nBase + wn * 64 + (lane & 3) * 2;
    #pragma unroll
    for (int mi = 0; mi < 2; mi++) {
        #pragma unroll
        for (int bp = 0; bp < 2; bp++) {
            #pragma unroll
            for (int s = 0; s < 4; s++) {
                int njp = 2*bp + (s >> 1);
                int q = s & 1;
                int ni_col = njp * 16 + q * 8;
                float v0 = acc[mi][4*bp + s][0], v1 = acc[mi][4*bp + s][1];
                float v2 = acc[mi][4*bp + s][2], v3 = acc[mi][4*bp + s][3];
                if (act) {
                    v0 = v0 / (1.0f + expf(-v0));
                    v1 = v1 / (1.0f + expf(-v1));
                    v2 = v2 / (1.0f + expf(-v2));
                    v3 = v3 / (1.0f + expf(-v3));
                }
                float* p0 = C + (size_t)(mrow + mi * 16) * CC + ncolbase + ni_col;
                float* p1 = p0 + 8 * CC;
                *(float2*)p0 = make_float2(v0, v1);
                *(float2*)p1 = make_float2(v2, v3);
            }
        }
    }
}

// ---------------------------------------------------------------------------
// 4) Chunked RWKV scan — 4-step unrolled, 2 heads per 128-thread block
// ---------------------------------------------------------------------------
__global__ __launch_bounds__(128) void scanA_kernel(
        const float* __restrict__ k, const float* __restrict__ v,
        const float* __restrict__ td, float* __restrict__ Sc) {
    int sub = threadIdx.x >> 6;          // 0/1: which head in this block
    int j = threadIdx.x & 63;
    int bh = blockIdx.x * 2 + sub;       // 0..127
    int chunk = blockIdx.y;
    int b = bh >> 5, h = bh & 31;

    float w = expf(-expf(td[h]));
    float S[HS];
    #pragma unroll
    for (int a = 0; a < HS; a++) S[a] = 0.0f;

    __shared__ float sk[2][8][HS], sv[2][8][HS];
    size_t base = (size_t)b * TTOT * CC + (size_t)h * HS;
    int t0 = chunk * TCH;

    #pragma unroll
    for (int q = 0; q < 4; q++) {
        size_t o0 = base + (size_t)(t0 + q) * CC;
        sk[sub][q][j] = k[o0 + j];
        sv[sub][q][j] = v[o0 + j];
    }
    __syncthreads();

    for (int i = 0; i < TCH; i += 4) {
        int pb = (i >> 2) & 1;
        int cb = pb * 4;
        int qb = (pb ^ 1) * 4;
        float kp[4], vp[4];
        #pragma unroll
        for (int q = 0; q < 4; q++) { kp[q] = 0.f; vp[q] = 0.f; }
        if (i + 4 < TCH) {
            #pragma unroll
            for (int q = 0; q < 4; q++) {
                size_t o2 = base + (size_t)(t0 + i + 4 + q) * CC;
                kp[q] = k[o2 + j]; vp[q] = v[o2 + j];
            }
        }
        float vj0 = sv[sub][cb][j],   vj1 = sv[sub][cb+1][j];
        float vj2 = sv[sub][cb+2][j], vj3 = sv[sub][cb+3][j];
        #pragma unroll
        for (int a = 0; a < HS; a++) {
            float s = S[a];
            s = fmaf(w, s, sk[sub][cb][a]   * vj0);
            s = fmaf(w, s, sk[sub][cb+1][a] * vj1);
            s = fmaf(w, s, sk[sub][cb+2][a] * vj2);
            S[a] = fmaf(w, s, sk[sub][cb+3][a] * vj3);
        }
        #pragma unroll
        for (int q = 0; q < 4; q++) {
            sk[sub][qb + q][j] = kp[q];
            sv[sub][qb + q][j] = vp[q];
        }
        __syncthreads();
    }
    size_t o = ((size_t)(chunk * 128 + bh) * HS) * HS + j;
    #pragma unroll
    for (int a = 0; a < HS; a++)
        Sc[o + (size_t)a * HS] = S[a];
}

__global__ __launch_bounds__(HS) void scanB_kernel(
        const float* __restrict__ s0, const float* __restrict__ Sc,
        const float* __restrict__ td, float* __restrict__ S0c) {
    int bh = blockIdx.x;
    int h = bh & 31;
    int j = threadIdx.x;
    float wT = expf(-expf(td[h]) * (float)TCH);

    float s[HS];
    #pragma unroll
    for (int a = 0; a < HS; a++)
        s[a] = s0[((size_t)bh * HS + a) * HS + j];

    for (int c = 0; c < NCHUNK; c++) {
        size_t o = ((size_t)(c * 128 + bh) * HS) * HS + j;
        #pragma unroll
        for (int a = 0; a < HS; a++) {
            S0c[o + (size_t)a * HS] = s[a];
            s[a] = fmaf(wT, s[a], Sc[o + (size_t)a * HS]);
        }
    }
}

__global__ __launch_bounds__(128) void scanC_kernel(
        const float* __restrict__ r, const float* __restrict__ k,
        const float* __restrict__ v, const float* __restrict__ td,
        const float* __restrict__ tf, const float* __restrict__ S0c,
        float* __restrict__ out) {
    int sub = threadIdx.x >> 6;
    int j = threadIdx.x & 63;
    int bh = blockIdx.x * 2 + sub;
    int chunk = blockIdx.y;
    int b = bh >> 5, h = bh & 31;

    float w = expf(-expf(td[h]));
    float u = tf[h];

    float s[HS];
    size_t so = ((size_t)(chunk * 128 + bh) * HS) * HS + j;
    #pragma unroll
    for (int a = 0; a < HS; a++)
        s[a] = S0c[so + (size_t)a * HS];

    __shared__ float sr[2][8][HS], sk[2][8][HS], sv[2][8][HS];
    size_t base = (size_t)b * TTOT * CC + (size_t)h * HS;
    int t0 = chunk * TCH;

    #pragma unroll
    for (int q = 0; q < 4; q++) {
        size_t o0 = base + (size_t)(t0 + q) * CC;
        sr[sub][q][j] = r[o0 + j]; sk[sub][q][j] = k[o0 + j]; sv[sub][q][j] = v[o0 + j];
    }
    __syncthreads();

    for (int i = 0; i < TCH; i += 4) {
        int pb = (i >> 2) & 1;
        int cb = pb * 4;
        int qb = (pb ^ 1) * 4;
        float rp[4], kp[4], vp[4];
        #pragma unroll
        for (int q = 0; q < 4; q++) { rp[q] = 0.f; kp[q] = 0.f; vp[q] = 0.f; }
        if (i + 4 < TCH) {
            #pragma unroll
            for (int q = 0; q < 4; q++) {
                size_t o2 = base + (size_t)(t0 + i + 4 + q) * CC;
                rp[q] = r[o2 + j]; kp[q] = k[o2 + j]; vp[q] = v[o2 + j];
            }
        }
        float vj0 = sv[sub][cb][j],   vj1 = sv[sub][cb+1][j];
        float vj2 = sv[sub][cb+2][j], vj3 = sv[sub][cb+3][j];
        float kr0 = 0.f, o0 = 0.f, kr1 = 0.f, o1 = 0.f;
        float kr2 = 0.f, o2a = 0.f, kr3 = 0.f, o3 = 0.f;
        #pragma unroll
        for (int a = 0; a < HS; a++) {
            float sa = s[a];
            float ra0 = sr[sub][cb][a],   ka0 = sk[sub][cb][a];
            float ra1 = sr[sub][cb+1][a], ka1 = sk[sub][cb+1][a];
            float ra2 = sr[sub][cb+2][a], ka2 = sk[sub][cb+2][a];
            float ra3 = sr[sub][cb+3][a], ka3 = sk[sub][cb+3][a];
            kr0 = fmaf(ra0, ka0, kr0);
            o0  = fmaf(ra0, sa, o0);
            sa  = fmaf(w, sa, ka0 * vj0);
            kr1 = fmaf(ra1, ka1, kr1);
            o1  = fmaf(ra1, sa, o1);
            sa  = fmaf(w, sa, ka1 * vj1);
            kr2 = fmaf(ra2, ka2, kr2);
            o2a = fmaf(ra2, sa, o2a);
            sa  = fmaf(w, sa, ka2 * vj2);
            kr3 = fmaf(ra3, ka3, kr3);
            o3  = fmaf(ra3, sa, o3);
            s[a] = fmaf(w, sa, ka3 * vj3);
        }
        size_t ocur = base + (size_t)(t0 + i) * CC;
        out[ocur + j]          = fmaf(u * kr0, vj0, o0);
        out[ocur + CC + j]     = fmaf(u * kr1, vj1, o1);
        out[ocur + 2*CC + j]   = fmaf(u * kr2, vj2, o2a);
        out[ocur + 3*CC + j]   = fmaf(u * kr3, vj3, o3);

        #pragma unroll
        for (int q = 0; q < 4; q++) {
            sr[sub][qb + q][j] = rp[q];
            sk[sub][qb + q][j] = kp[q];
            sv[sub][qb + q][j] = vp[q];
        }
        __syncthreads();
    }
}

// ---------------------------------------------------------------------------
// 5) GroupNorm * gamma + beta, * g -> fp16 y
// ---------------------------------------------------------------------------
__global__ void gn_mul_kernel(const float* __restrict__ x, const float* __restrict__ g,
                              const float* __restrict__ gamma, const float* __restrict__ beta,
                              f16* __restrict__ y) {
    int warp = (int)((blockIdx.x * blockDim.x + threadIdx.x) >> 5);
    int lane = threadIdx.x & 31;
    if (warp >= ROWS * NH) return;
    int row = warp >> 5;
    int h   = warp & 31;
    size_t base = (size_t)row * CC + (size_t)h * HS;

    float x0 = x[base + lane]      * 0.125f;
    float x1 = x[base + lane + 32] * 0.125f;
    float sum = x0 + x1;
    float sq  = fmaf(x0, x0, x1 * x1);
    #pragma unroll
    for (int o = 16; o; o >>= 1) {
        sum += __shfl_xor_sync(0xffffffffu, sum, o);
        sq  += __shfl_xor_sync(0xffffffffu, sq,  o);
    }
    float mu  = sum * (1.0f / 64.0f);
    float var = sq  * (1.0f / 64.0f) - mu * mu;
    float inv = rsqrtf(var + 1e-5f);

    int c0 = h * HS + lane, c1 = c0 + 32;
    float y0 = ((x0 - mu) * inv * gamma[c0] + beta[c0]) * g[base + lane];
    float y1 = ((x1 - mu) * inv * gamma[c1] + beta[c1]) * g[base + lane + 32];
    y[base + lane]      = __float2half_rn(y0);
    y[base + lane + 32] = __float2half_rn(y1);
}

// ---------------------------------------------------------------------------
// Launcher
// ---------------------------------------------------------------------------
extern "C" void kernel_launch(void* const* d_in, const int* in_sizes, int n_in,
                              void* d_out, int out_size) {
    const float* x     = (const float*)d_in[0];
    const float* Wr    = (const float*)d_in[1];
    const float* Wk    = (const float*)d_in[2];
    const float* Wv    = (const float*)d_in[3];
    const float* Wg    = (const float*)d_in[4];
    const float* Wo    = (const float*)d_in[5];
    const float* gamma = (const float*)d_in[6];
    const float* beta  = (const float*)d_in[7];
    const float* tmk   = (const float*)d_in[8];
    const float* tmv   = (const float*)d_in[9];
    const float* tmr   = (const float*)d_in[10];
    const float* tmg   = (const float*)d_in[11];
    const float* td    = (const float*)d_in[12];
    const float* tf    = (const float*)d_in[13];
    const float* s0    = (const float*)d_in[14];
    float* out = (float*)d_out;

    static bool attr_done = false;
    if (!attr_done) {
        cudaFuncSetAttribute(tc_gemm_b, cudaFuncAttributeMaxDynamicSharedMemorySize, SMEM_B);
        attr_done = true;
    }

    f16 *xr,*xk,*xv,*xg,*yb;
    f16 *wrt,*wkt,*wvt,*wgt,*wot;
    float *rb,*kb,*vb,*gb,*ao,*Sc,*S0c;
    cudaGetSymbolAddress((void**)&xr, g_xr);
    cudaGetSymbolAddress((void**)&xk, g_xk);
    cudaGetSymbolAddress((void**)&xv, g_xv);
    cudaGetSymbolAddress((void**)&xg, g_xg);
    cudaGetSymbolAddress((void**)&yb, g_y);
    cudaGetSymbolAddress((void**)&rb, g_r); cudaGetSymbolAddress((void**)&kb, g_k);
    cudaGetSymbolAddress((void**)&vb, g_v); cudaGetSymbolAddress((void**)&gb, g_g);
    cudaGetSymbolAddress((void**)&ao, g_ao);
    cudaGetSymbolAddress((void**)&Sc, g_Sc); cudaGetSymbolAddress((void**)&S0c, g_S0c);
    cudaGetSymbolAddress((void**)&wrt, g_WrT);
    cudaGetSymbolAddress((void**)&wkt, g_WkT);
    cudaGetSymbolAddress((void**)&wvt, g_WvT);
    cudaGetSymbolAddress((void**)&wgt, g_WgT);
    cudaGetSymbolAddress((void**)&wot, g_WoT);

    WB wb;
    wb.W[0] = Wr; wb.W[1] = Wk; wb.W[2] = Wv; wb.W[3] = Wg; wb.W[4] = Wo;
    wb.O[0] = wrt; wb.O[1] = wkt; wb.O[2] = wvt; wb.O[3] = wgt; wb.O[4] = wot;
    wprep_b<<<dim3(CC/32, CC/32, 5), dim3(32, 8)>>>(wb);

    int mixBlocks = (int)((ELEMS / 4 + 255) / 256);
    mix_kernel<<<mixBlocks, 256>>>(x, tmk, tmv, tmr, tmg, xk, xv, xr, xg);

    GB g4;
    g4.Ap[0] = xr; g4.Bp[0] = wrt; g4.Cp[0] = rb; g4.act[0] = 0;
    g4.Ap[1] = xk; g4.Bp[1] = wkt; g4.Cp[1] = kb; g4.act[1] = 0;
    g4.Ap[2] = xv; g4.Bp[2] = wvt; g4.Cp[2] = vb; g4.act[2] = 0;
    g4.Ap[3] = xg; g4.Bp[3] = wgt; g4.Cp[3] = gb; g4.act[3] = 1;
    tc_gemm_b<<<dim3(CC/BN, ROWS/BM, 4), 256, SMEM_B>>>(g4);

    dim3 sg(64, NCHUNK);                       // 2 heads per block
    scanA_kernel<<<sg, 128>>>(kb, vb, td, Sc);
    scanB_kernel<<<128, HS>>>(s0, Sc, td, S0c);
    scanC_kernel<<<sg, 128>>>(rb, kb, vb, td, tf, S0c, ao);

    gn_mul_kernel<<<(ROWS * NH) / 8, 256>>>(ao, gb, gamma, beta, yb);

    GB g1;
    g1.Ap[0] = yb; g1.Bp[0] = wot; g1.Cp[0] = out; g1.act[0] = 0;
    g1.Ap[1] = yb; g1.Bp[1] = wot; g1.Cp[1] = out; g1.act[1] = 0;
    g1.Ap[2] = yb; g1.Bp[2] = wot; g1.Cp[2] = out; g1.act[2] = 0;
    g1.Ap[3] = yb; g1.Bp[3] = wot; g1.Cp[3] = out; g1.act[3] = 0;
    tc_gemm_b<<<dim3(CC/BN, ROWS/BM, 1), 256, SMEM_B>>>(g1);
}

// round 15
// speedup vs baseline: 1.1029x; 1.1029x over previous
#include <cuda_runtime.h>
#include <cuda_fp16.h>
#include <cstdint>
#include <math.h>

#define BB 4
#define TTOT 4096
#define CC 2048
#define NH 32
#define HS 64
#define ROWS (BB*TTOT)
#define ELEMS ((size_t)ROWS*(size_t)CC)
#define NCHUNK 32
#define TCH (TTOT/NCHUNK)      // 128

typedef __half f16;

#define BM 128
#define BN 128
#define BKT 32
#define TILE_B (128*80)
#define STAGE_B (2*TILE_B)
#define NSTG 4
#define SMEM_B (NSTG*STAGE_B)
#define KTILES (CC/BKT)

// ---------------------------------------------------------------------------
// Scratch
// ---------------------------------------------------------------------------
__device__ f16 g_xr[ELEMS];
__device__ f16 g_xk[ELEMS];
__device__ f16 g_xv[ELEMS];
__device__ f16 g_xg[ELEMS];
__device__ f16 g_y[ELEMS];
__device__ float g_r[ELEMS];
__device__ float g_k[ELEMS];
__device__ float g_v[ELEMS];
__device__ float g_g[ELEMS];
__device__ float g_ao[ELEMS];
__device__ f16 g_WrT[CC*CC];
__device__ f16 g_WkT[CC*CC];
__device__ f16 g_WvT[CC*CC];
__device__ f16 g_WgT[CC*CC];
__device__ f16 g_WoT[CC*CC];
__device__ float g_Sc[(size_t)NCHUNK*128*HS*HS];
__device__ float g_S0c[(size_t)NCHUNK*128*HS*HS];

// ---------------------------------------------------------------------------
// helpers
// ---------------------------------------------------------------------------
__device__ __forceinline__ uint32_t smem_u32(const void* p) {
    uint32_t a;
    asm("{ .reg .u64 t; cvta.to.shared.u64 t, %1; cvt.u32.u64 %0, t; }" : "=r"(a) : "l"(p));
    return a;
}
__device__ __forceinline__ void cpa16(uint32_t dst, const void* src) {
    asm volatile("cp.async.cg.shared.global [%0], [%1], 16;" :: "r"(dst), "l"(src));
}
__device__ __forceinline__ void cp_commit() {
    asm volatile("cp.async.commit_group;" ::: "memory");
}
template<int N> __device__ __forceinline__ void cp_wait() {
    asm volatile("cp.async.wait_group %0;" :: "n"(N) : "memory");
}
__device__ __forceinline__ void ldsm4(uint32_t (&r)[4], uint32_t addr) {
    asm volatile("ldmatrix.sync.aligned.m8n8.x4.shared.b16 {%0,%1,%2,%3}, [%4];"
                 : "=r"(r[0]), "=r"(r[1]), "=r"(r[2]), "=r"(r[3]) : "r"(addr));
}
__device__ __forceinline__ void mma_f16(float (&c)[4], const uint32_t (&a)[4],
                                        uint32_t b0, uint32_t b1) {
    asm volatile(
        "mma.sync.aligned.m16n8k16.row.col.f32.f16.f16.f32 "
        "{%0,%1,%2,%3}, {%4,%5,%6,%7}, {%8,%9}, {%0,%1,%2,%3};"
        : "+f"(c[0]), "+f"(c[1]), "+f"(c[2]), "+f"(c[3])
        : "r"(a[0]), "r"(a[1]), "r"(a[2]), "r"(a[3]), "r"(b0), "r"(b1));
}
__device__ __forceinline__ uint32_t pack_h2(float a, float b) {
    __half2 h = __floats2half2_rn(a, b);
    return *(uint32_t*)&h;
}
// ---- packed f32x2 (sm_100 family) ----
__device__ __forceinline__ uint64_t pk2(float x) {
    uint64_t r; asm("mov.b64 %0, {%1, %1};" : "=l"(r) : "f"(x)); return r;
}
__device__ __forceinline__ uint64_t pk2b(float lo, float hi) {
    uint64_t r; asm("mov.b64 %0, {%1, %2};" : "=l"(r) : "f"(lo), "f"(hi)); return r;
}
__device__ __forceinline__ void unpk2(uint64_t p, float& lo, float& hi) {
    asm("mov.b64 {%0, %1}, %2;" : "=f"(lo), "=f"(hi) : "l"(p));
}
__device__ __forceinline__ uint64_t mul2(uint64_t a, uint64_t b) {
    uint64_t r; asm("mul.rn.f32x2 %0, %1, %2;" : "=l"(r) : "l"(a), "l"(b)); return r;
}
__device__ __forceinline__ uint64_t fma2(uint64_t a, uint64_t b, uint64_t c) {
    uint64_t r; asm("fma.rn.f32x2 %0, %1, %2, %3;" : "=l"(r) : "l"(a), "l"(b), "l"(c)); return r;
}

// ---------------------------------------------------------------------------
// 1) Token-shift mixing -> fp16 planes
// ---------------------------------------------------------------------------
__global__ void mix_kernel(const float* __restrict__ x,
                           const float* __restrict__ tmk, const float* __restrict__ tmv,
                           const float* __restrict__ tmr, const float* __restrict__ tmg,
                           f16* __restrict__ xk, f16* __restrict__ xv,
                           f16* __restrict__ xr, f16* __restrict__ xg) {
    size_t i4 = (size_t)blockIdx.x * blockDim.x + threadIdx.x;
    if (i4 >= ELEMS / 4) return;
    size_t idx = i4 * 4;
    int c = (int)(idx % CC);
    int t = (int)((idx / CC) % TTOT);

    float4 xc = *(const float4*)(x + idx);
    float4 xp = make_float4(0.f, 0.f, 0.f, 0.f);
    if (t != 0) xp = *(const float4*)(x + idx - CC);
    float4 mk = *(const float4*)(tmk + c);
    float4 mv = *(const float4*)(tmv + c);
    float4 mr = *(const float4*)(tmr + c);
    float4 mg = *(const float4*)(tmg + c);

    uint2 o;
    o.x = pack_h2(xc.x * mk.x + xp.x * (1.f - mk.x), xc.y * mk.y + xp.y * (1.f - mk.y));
    o.y = pack_h2(xc.z * mk.z + xp.z * (1.f - mk.z), xc.w * mk.w + xp.w * (1.f - mk.w));
    *(uint2*)(xk + idx) = o;
    o.x = pack_h2(xc.x * mv.x + xp.x * (1.f - mv.x), xc.y * mv.y + xp.y * (1.f - mv.y));
    o.y = pack_h2(xc.z * mv.z + xp.z * (1.f - mv.z), xc.w * mv.w + xp.w * (1.f - mv.w));
    *(uint2*)(xv + idx) = o;
    o.x = pack_h2(xc.x * mr.x + xp.x * (1.f - mr.x), xc.y * mr.y + xp.y * (1.f - mr.y));
    o.y = pack_h2(xc.z * mr.z + xp.z * (1.f - mr.z), xc.w * mr.w + xp.w * (1.f - mr.w));
    *(uint2*)(xr + idx) = o;
    o.x = pack_h2(xc.x * mg.x + xp.x * (1.f - mg.x), xc.y * mg.y + xp.y * (1.f - mg.y));
    o.y = pack_h2(xc.z * mg.z + xp.z * (1.f - mg.z), xc.w * mg.w + xp.w * (1.f - mg.w));
    *(uint2*)(xg + idx) = o;
}

// ---------------------------------------------------------------------------
// 2) Weight prep (batched over grid.z)
// ---------------------------------------------------------------------------
struct WB { const float* W[5]; f16* O[5]; };

__global__ void wprep_b(WB wb) {
    const float* __restrict__ W = wb.W[blockIdx.z];
    f16* __restrict__ WT = wb.O[blockIdx.z];
    __shared__ float t[32][33];
    int n0 = blockIdx.x * 32, k0 = blockIdx.y * 32;
    int tx = threadIdx.x, ty = threadIdx.y;
    #pragma unroll
    for (int r = ty; r < 32; r += 8)
        t[r][tx] = W[(size_t)(k0 + r) * CC + n0 + tx];
    __syncthreads();
    #pragma unroll
    for (int r = ty; r < 32; r += 8)
        WT[(size_t)(n0 + r) * CC + k0 + tx] = __float2half_rn(t[tx][r]);
}

// ---------------------------------------------------------------------------
// 3) Batched fp16 GEMM — R11 schedule (frozen local optimum)
// ---------------------------------------------------------------------------
struct GB {
    const f16* Ap[4]; const f16* Bp[4];
    float* Cp[4]; int act[4];
};

__global__ __launch_bounds__(256, 2) void tc_gemm_b(GB gb) {
    int z = blockIdx.z;
    const f16* __restrict__ A = gb.Ap[z];
    const f16* __restrict__ B = gb.Bp[z];
    float* __restrict__ C = gb.Cp[z];
    int act = gb.act[z];

    extern __shared__ char smem[];
    uint32_t sb = smem_u32(smem);

    int tid = threadIdx.x;
    int lane = tid & 31;
    int wm = (tid >> 5) & 3;
    int wn = tid >> 7;
    int mBase = blockIdx.y * BM;
    int nBase = blockIdx.x * BN;

    uint32_t dA = (uint32_t)((tid >> 2) * 80 + (tid & 3) * 16);
    const f16* pA = A + (size_t)(mBase + (tid >> 2)) * CC + (tid & 3) * 8;
    const f16* pB = B + (size_t)(nBase + (tid >> 2)) * CC + (tid & 3) * 8;

    float acc[2][8][4];
    #pragma unroll
    for (int i = 0; i < 2; i++)
        #pragma unroll
        for (int j = 0; j < 8; j++)
            #pragma unroll
            for (int q = 0; q < 4; q++) acc[i][j][q] = 0.0f;

    #pragma unroll
    for (int s = 0; s < NSTG - 1; s++) {
        uint32_t stb = sb + s * STAGE_B;
        int k0 = s * BKT;
        cpa16(stb + dA,                 pA + k0);
        cpa16(stb + dA + 5120,          pA + 64 * CC + k0);
        cpa16(stb + TILE_B + dA,        pB + k0);
        cpa16(stb + TILE_B + dA + 5120, pB + 64 * CC + k0);
        cp_commit();
    }

    uint32_t aRow = (uint32_t)(wm * 32 + ((lane >> 3) & 1) * 8 + (lane & 7));
    uint32_t aCol = (uint32_t)((lane >> 4) * 16);
    uint32_t bRow = (uint32_t)(wn * 64 + (lane >> 4) * 8 + (lane & 7));
    uint32_t bCol = (uint32_t)(((lane >> 3) & 1) * 16);
    int ksSkew = wm & 1;

    for (int kt = 0; kt < KTILES; kt++) {
        cp_wait<NSTG - 2>();
        __syncthreads();

        int nt = kt + NSTG - 1;
        if (nt < KTILES) {
            uint32_t stb = sb + (nt & (NSTG - 1)) * STAGE_B;
            int k0 = nt * BKT;
            cpa16(stb + dA,                 pA + k0);
            cpa16(stb + dA + 5120,          pA + 64 * CC + k0);
            cpa16(stb + TILE_B + dA,        pB + k0);
            cpa16(stb + TILE_B + dA + 5120, pB + 64 * CC + k0);
        }
        cp_commit();

        uint32_t stg = sb + (kt & (NSTG - 1)) * STAGE_B;

        #pragma unroll
        for (int kss = 0; kss < 2; kss++) {
            int ks = kss ^ ksSkew;
            uint32_t a_f[2][4];
            #pragma unroll
            for (int mi = 0; mi < 2; mi++) {
                uint32_t ra = (aRow + mi * 16) * 80 + aCol + ks * 32;
                ldsm4(a_f[mi], stg + ra);
            }
            #pragma unroll
            for (int bp = 0; bp < 2; bp++) {
                uint32_t b0[4], b1[4];
                {
                    uint32_t rb0 = (bRow + (2*bp + 0) * 16) * 80 + bCol + ks * 32;
                    uint32_t rb1 = (bRow + (2*bp + 1) * 16) * 80 + bCol + ks * 32;
                    ldsm4(b0, stg + TILE_B + rb0);
                    ldsm4(b1, stg + TILE_B + rb1);
                }
                #pragma unroll
                for (int mi = 0; mi < 2; mi++) {
                    mma_f16(acc[mi][4*bp + 0], a_f[mi], b0[0], b0[1]);
                    mma_f16(acc[mi][4*bp + 1], a_f[mi], b0[2], b0[3]);
                    mma_f16(acc[mi][4*bp + 2], a_f[mi], b1[0], b1[1]);
                    mma_f16(acc[mi][4*bp + 3], a_f[mi], b1[2], b1[3]);
                }
            }
        }
    }

    int mrow = mBase + wm * 32 + (lane >> 2);
    int ncolbase = nBase + wn * 64 + (lane & 3) * 2;
    #pragma unroll
    for (int mi = 0; mi < 2; mi++) {
        #pragma unroll
        for (int bp = 0; bp < 2; bp++) {
            #pragma unroll
            for (int s = 0; s < 4; s++) {
                int njp = 2*bp + (s >> 1);
                int q = s & 1;
                int ni_col = njp * 16 + q * 8;
                float v0 = acc[mi][4*bp + s][0], v1 = acc[mi][4*bp + s][1];
                float v2 = acc[mi][4*bp + s][2], v3 = acc[mi][4*bp + s][3];
                if (act) {
                    v0 = v0 / (1.0f + expf(-v0));
                    v1 = v1 / (1.0f + expf(-v1));
                    v2 = v2 / (1.0f + expf(-v2));
                    v3 = v3 / (1.0f + expf(-v3));
                }
                float* p0 = C + (size_t)(mrow + mi * 16) * CC + ncolbase + ni_col;
                float* p1 = p0 + 8 * CC;
                *(float2*)p0 = make_float2(v0, v1);
                *(float2*)p1 = make_float2(v2, v3);
            }
        }
    }
}

// ---------------------------------------------------------------------------
// 4) Chunked RWKV scan — 4-step unrolled + packed f32x2 state math
// ---------------------------------------------------------------------------
__global__ __launch_bounds__(HS) void scanA_kernel(
        const float* __restrict__ k, const float* __restrict__ v,
        const float* __restrict__ td, float* __restrict__ Sc) {
    int bh = blockIdx.x;
    int chunk = blockIdx.y;
    int b = bh >> 5, h = bh & 31;
    int j = threadIdx.x;

    float w = expf(-expf(td[h]));
    uint64_t w2 = pk2(w);
    uint64_t S2[32];
    #pragma unroll
    for (int p = 0; p < 32; p++) S2[p] = 0ull;

    __shared__ __align__(16) float sk[8][HS], sv[8][HS];
    size_t base = (size_t)b * TTOT * CC + (size_t)h * HS;
    int t0 = chunk * TCH;

    #pragma unroll
    for (int q = 0; q < 4; q++) {
        size_t o0 = base + (size_t)(t0 + q) * CC;
        sk[q][j] = k[o0 + j];
        sv[q][j] = v[o0 + j];
    }
    __syncthreads();

    for (int i = 0; i < TCH; i += 4) {
        int pb = (i >> 2) & 1;
        int cb = pb * 4;
        int qb = (pb ^ 1) * 4;
        float kp[4], vp[4];
        #pragma unroll
        for (int q = 0; q < 4; q++) { kp[q] = 0.f; vp[q] = 0.f; }
        if (i + 4 < TCH) {
            #pragma unroll
            for (int q = 0; q < 4; q++) {
                size_t o2 = base + (size_t)(t0 + i + 4 + q) * CC;
                kp[q] = k[o2 + j]; vp[q] = v[o2 + j];
            }
        }
        uint64_t vv0 = pk2(sv[cb][j]),   vv1 = pk2(sv[cb+1][j]);
        uint64_t vv2 = pk2(sv[cb+2][j]), vv3 = pk2(sv[cb+3][j]);
        const uint64_t* k0r = (const uint64_t*)sk[cb];
        const uint64_t* k1r = (const uint64_t*)sk[cb+1];
        const uint64_t* k2r = (const uint64_t*)sk[cb+2];
        const uint64_t* k3r = (const uint64_t*)sk[cb+3];
        #pragma unroll
        for (int p = 0; p < 32; p++) {
            uint64_t s2 = S2[p];
            s2 = fma2(w2, s2, mul2(k0r[p], vv0));
            s2 = fma2(w2, s2, mul2(k1r[p], vv1));
            s2 = fma2(w2, s2, mul2(k2r[p], vv2));
            S2[p] = fma2(w2, s2, mul2(k3r[p], vv3));
        }
        #pragma unroll
        for (int q = 0; q < 4; q++) {
            sk[qb + q][j] = kp[q];
            sv[qb + q][j] = vp[q];
        }
        __syncthreads();
    }
    size_t o = ((size_t)(chunk * 128 + bh) * HS) * HS + j;
    #pragma unroll
    for (int p = 0; p < 32; p++) {
        float lo, hi;
        unpk2(S2[p], lo, hi);
        Sc[o + (size_t)(2*p)   * HS] = lo;
        Sc[o + (size_t)(2*p+1) * HS] = hi;
    }
}

__global__ __launch_bounds__(HS) void scanB_kernel(
        const float* __restrict__ s0, const float* __restrict__ Sc,
        const float* __restrict__ td, float* __restrict__ S0c) {
    int bh = blockIdx.x;
    int h = bh & 31;
    int j = threadIdx.x;
    float wT = expf(-expf(td[h]) * (float)TCH);

    float s[HS];
    #pragma unroll
    for (int a = 0; a < HS; a++)
        s[a] = s0[((size_t)bh * HS + a) * HS + j];

    for (int c = 0; c < NCHUNK; c++) {
        size_t o = ((size_t)(c * 128 + bh) * HS) * HS + j;
        #pragma unroll
        for (int a = 0; a < HS; a++) {
            S0c[o + (size_t)a * HS] = s[a];
            s[a] = fmaf(wT, s[a], Sc[o + (size_t)a * HS]);
        }
    }
}

__global__ __launch_bounds__(HS) void scanC_kernel(
        const float* __restrict__ r, const float* __restrict__ k,
        const float* __restrict__ v, const float* __restrict__ td,
        const float* __restrict__ tf, const float* __restrict__ S0c,
        float* __restrict__ out) {
    int bh = blockIdx.x;
    int chunk = blockIdx.y;
    int b = bh >> 5, h = bh & 31;
    int j = threadIdx.x;

    float w = expf(-expf(td[h]));
    float u = tf[h];
    uint64_t w2 = pk2(w);

    uint64_t S2[32];
    size_t so = ((size_t)(chunk * 128 + bh) * HS) * HS + j;
    #pragma unroll
    for (int p = 0; p < 32; p++) {
        float lo = S0c[so + (size_t)(2*p)   * HS];
        float hi = S0c[so + (size_t)(2*p+1) * HS];
        S2[p] = pk2b(lo, hi);
    }

    __shared__ __align__(16) float sr[8][HS], sk[8][HS], sv[8][HS];
    size_t base = (size_t)b * TTOT * CC + (size_t)h * HS;
    int t0 = chunk * TCH;

    #pragma unroll
    for (int q = 0; q < 4; q++) {
        size_t o0 = base + (size_t)(t0 + q) * CC;
        sr[q][j] = r[o0 + j]; sk[q][j] = k[o0 + j]; sv[q][j] = v[o0 + j];
    }
    __syncthreads();

    for (int i = 0; i < TCH; i += 4) {
        int pb = (i >> 2) & 1;
        int cb = pb * 4;
        int qb = (pb ^ 1) * 4;
        float rp[4], kp[4], vp[4];
        #pragma unroll
        for (int q = 0; q < 4; q++) { rp[q] = 0.f; kp[q] = 0.f; vp[q] = 0.f; }
        if (i + 4 < TCH) {
            #pragma unroll
            for (int q = 0; q < 4; q++) {
                size_t o2 = base + (size_t)(t0 + i + 4 + q) * CC;
                rp[q] = r[o2 + j]; kp[q] = k[o2 + j]; vp[q] = v[o2 + j];
            }
        }
        float vj0 = sv[cb][j],   vj1 = sv[cb+1][j];
        float vj2 = sv[cb+2][j], vj3 = sv[cb+3][j];
        uint64_t vv0 = pk2(vj0), vv1 = pk2(vj1), vv2 = pk2(vj2), vv3 = pk2(vj3);
        const uint64_t* r0r = (const uint64_t*)sr[cb];
        const uint64_t* r1r = (const uint64_t*)sr[cb+1];
        const uint64_t* r2r = (const uint64_t*)sr[cb+2];
        const uint64_t* r3r = (const uint64_t*)sr[cb+3];
        const uint64_t* k0r = (const uint64_t*)sk[cb];
        const uint64_t* k1r = (const uint64_t*)sk[cb+1];
        const uint64_t* k2r = (const uint64_t*)sk[cb+2];
        const uint64_t* k3r = (const uint64_t*)sk[cb+3];
        uint64_t kr0 = 0ull, o0 = 0ull, kr1 = 0ull, o1 = 0ull;
        uint64_t kr2 = 0ull, o2 = 0ull, kr3 = 0ull, o3 = 0ull;
        #pragma unroll
        for (int p = 0; p < 32; p++) {
            uint64_t sa = S2[p];
            uint64_t r0 = r0r[p], k0 = k0r[p];
            kr0 = fma2(r0, k0, kr0);
            o0  = fma2(r0, sa, o0);
            sa  = fma2(w2, sa, mul2(k0, vv0));
            uint64_t r1 = r1r[p], k1 = k1r[p];
            kr1 = fma2(r1, k1, kr1);
            o1  = fma2(r1, sa, o1);
            sa  = fma2(w2, sa, mul2(k1, vv1));
            uint64_t r2 = r2r[p], k2 = k2r[p];
            kr2 = fma2(r2, k2, kr2);
            o2  = fma2(r2, sa, o2);
            sa  = fma2(w2, sa, mul2(k2, vv2));
            uint64_t r3 = r3r[p], k3 = k3r[p];
            kr3 = fma2(r3, k3, kr3);
            o3  = fma2(r3, sa, o3);
            S2[p] = fma2(w2, sa, mul2(k3, vv3));
        }
        float lo, hi;
        float kr0f, o0f, kr1f, o1f, kr2f, o2f, kr3f, o3f;
        unpk2(kr0, lo, hi); kr0f = lo + hi;
        unpk2(o0,  lo, hi); o0f  = lo + hi;
        unpk2(kr1, lo, hi); kr1f = lo + hi;
        unpk2(o1,  lo, hi); o1f  = lo + hi;
        unpk2(kr2, lo, hi); kr2f = lo + hi;
        unpk2(o2,  lo, hi); o2f  = lo + hi;
        unpk2(kr3, lo, hi); kr3f = lo + hi;
        unpk2(o3,  lo, hi); o3f  = lo + hi;

        size_t ocur = base + (size_t)(t0 + i) * CC;
        out[ocur + j]        = fmaf(u * kr0f, vj0, o0f);
        out[ocur + CC + j]   = fmaf(u * kr1f, vj1, o1f);
        out[ocur + 2*CC + j] = fmaf(u * kr2f, vj2, o2f);
        out[ocur + 3*CC + j] = fmaf(u * kr3f, vj3, o3f);

        #pragma unroll
        for (int q = 0; q < 4; q++) {
            sr[qb + q][j] = rp[q]; sk[qb + q][j] = kp[q]; sv[qb + q][j] = vp[q];
        }
        __syncthreads();
    }
}

// ---------------------------------------------------------------------------
// 5) GroupNorm * gamma + beta, * g -> fp16 y
// ---------------------------------------------------------------------------
__global__ void gn_mul_kernel(const float* __restrict__ x, const float* __restrict__ g,
                              const float* __restrict__ gamma, const float* __restrict__ beta,
                              f16* __restrict__ y) {
    int warp = (int)((blockIdx.x * blockDim.x + threadIdx.x) >> 5);
    int lane = threadIdx.x & 31;
    if (warp >= ROWS * NH) return;
    int row = warp >> 5;
    int h   = warp & 31;
    size_t base = (size_t)row * CC + (size_t)h * HS;

    float x0 = x[base + lane]      * 0.125f;
    float x1 = x[base + lane + 32] * 0.125f;
    float sum = x0 + x1;
    float sq  = fmaf(x0, x0, x1 * x1);
    #pragma unroll
    for (int o = 16; o; o >>= 1) {
        sum += __shfl_xor_sync(0xffffffffu, sum, o);
        sq  += __shfl_xor_sync(0xffffffffu, sq,  o);
    }
    float mu  = sum * (1.0f / 64.0f);
    float var = sq  * (1.0f / 64.0f) - mu * mu;
    float inv = rsqrtf(var + 1e-5f);

    int c0 = h * HS + lane, c1 = c0 + 32;
    float y0 = ((x0 - mu) * inv * gamma[c0] + beta[c0]) * g[base + lane];
    float y1 = ((x1 - mu) * inv * gamma[c1] + beta[c1]) * g[base + lane + 32];
    y[base + lane]      = __float2half_rn(y0);
    y[base + lane + 32] = __float2half_rn(y1);
}

// ---------------------------------------------------------------------------
// Launcher
// ---------------------------------------------------------------------------
extern "C" void kernel_launch(void* const* d_in, const int* in_sizes, int n_in,
                              void* d_out, int out_size) {
    const float* x     = (const float*)d_in[0];
    const float* Wr    = (const float*)d_in[1];
    const float* Wk    = (const float*)d_in[2];
    const float* Wv    = (const float*)d_in[3];
    const float* Wg    = (const float*)d_in[4];
    const float* Wo    = (const float*)d_in[5];
    const float* gamma = (const float*)d_in[6];
    const float* beta  = (const float*)d_in[7];
    const float* tmk   = (const float*)d_in[8];
    const float* tmv   = (const float*)d_in[9];
    const float* tmr   = (const float*)d_in[10];
    const float* tmg   = (const float*)d_in[11];
    const float* td    = (const float*)d_in[12];
    const float* tf    = (const float*)d_in[13];
    const float* s0    = (const float*)d_in[14];
    float* out = (float*)d_out;

    static bool attr_done = false;
    if (!attr_done) {
        cudaFuncSetAttribute(tc_gemm_b, cudaFuncAttributeMaxDynamicSharedMemorySize, SMEM_B);
        attr_done = true;
    }

    f16 *xr,*xk,*xv,*xg,*yb;
    f16 *wrt,*wkt,*wvt,*wgt,*wot;
    float *rb,*kb,*vb,*gb,*ao,*Sc,*S0c;
    cudaGetSymbolAddress((void**)&xr, g_xr);
    cudaGetSymbolAddress((void**)&xk, g_xk);
    cudaGetSymbolAddress((void**)&xv, g_xv);
    cudaGetSymbolAddress((void**)&xg, g_xg);
    cudaGetSymbolAddress((void**)&yb, g_y);
    cudaGetSymbolAddress((void**)&rb, g_r); cudaGetSymbolAddress((void**)&kb, g_k);
    cudaGetSymbolAddress((void**)&vb, g_v); cudaGetSymbolAddress((void**)&gb, g_g);
    cudaGetSymbolAddress((void**)&ao, g_ao);
    cudaGetSymbolAddress((void**)&Sc, g_Sc); cudaGetSymbolAddress((void**)&S0c, g_S0c);
    cudaGetSymbolAddress((void**)&wrt, g_WrT);
    cudaGetSymbolAddress((void**)&wkt, g_WkT);
    cudaGetSymbolAddress((void**)&wvt, g_WvT);
    cudaGetSymbolAddress((void**)&wgt, g_WgT);
    cudaGetSymbolAddress((void**)&wot, g_WoT);

    WB wb;
    wb.W[0] = Wr; wb.W[1] = Wk; wb.W[2] = Wv; wb.W[3] = Wg; wb.W[4] = Wo;
    wb.O[0] = wrt; wb.O[1] = wkt; wb.O[2] = wvt; wb.O[3] = wgt; wb.O[4] = wot;
    wprep_b<<<dim3(CC/32, CC/32, 5), dim3(32, 8)>>>(wb);

    int mixBlocks = (int)((ELEMS / 4 + 255) / 256);
    mix_kernel<<<mixBlocks, 256>>>(x, tmk, tmv, tmr, tmg, xk, xv, xr, xg);

    GB g4;
    g4.Ap[0] = xr; g4.Bp[0] = wrt; g4.Cp[0] = rb; g4.act[0] = 0;
    g4.Ap[1] = xk; g4.Bp[1] = wkt; g4.Cp[1] = kb; g4.act[1] = 0;
    g4.Ap[2] = xv; g4.Bp[2] = wvt; g4.Cp[2] = vb; g4.act[2] = 0;
    g4.Ap[3] = xg; g4.Bp[3] = wgt; g4.Cp[3] = gb; g4.act[3] = 1;
    tc_gemm_b<<<dim3(CC/BN, ROWS/BM, 4), 256, SMEM_B>>>(g4);

    dim3 sg(128, NCHUNK);
    scanA_kernel<<<sg, HS>>>(kb, vb, td, Sc);
    scanB_kernel<<<128, HS>>>(s0, Sc, td, S0c);
    scanC_kernel<<<sg, HS>>>(rb, kb, vb, td, tf, S0c, ao);

    gn_mul_kernel<<<(ROWS * NH) / 8, 256>>>(ao, gb, gamma, beta, yb);

    GB g1;
    g1.Ap[0] = yb; g1.Bp[0] = wot; g1.Cp[0] = out; g1.act[0] = 0;
    g1.Ap[1] = yb; g1.Bp[1] = wot; g1.Cp[1] = out; g1.act[1] = 0;
    g1.Ap[2] = yb; g1.Bp[2] = wot; g1.Cp[2] = out; g1.act[2] = 0;
    g1.Ap[3] = yb; g1.Bp[3] = wot; g1.Cp[3] = out; g1.act[3] = 0;
    tc_gemm_b<<<dim3(CC/BN, ROWS/BM, 1), 256, SMEM_B>>>(g1);
}

// round 16
// speedup vs baseline: 1.2253x; 1.1110x over previous
#include <cuda_runtime.h>
#include <cuda_fp16.h>
#include <cstdint>
#include <math.h>

#define BB 4
#define TTOT 4096
#define CC 2048
#define NH 32
#define HS 64
#define ROWS (BB*TTOT)
#define ELEMS ((size_t)ROWS*(size_t)CC)
#define NCHUNK 32
#define TCH (TTOT/NCHUNK)      // 128

typedef __half f16;

#define BM 128
#define BN 128
#define BKT 32
#define TILE_B (128*80)
#define STAGE_B (2*TILE_B)
#define NSTG 4
#define SMEM_B (NSTG*STAGE_B)
#define KTILES (CC/BKT)

// ---------------------------------------------------------------------------
// Scratch
// ---------------------------------------------------------------------------
__device__ f16 g_xr[ELEMS];
__device__ f16 g_xk[ELEMS];
__device__ f16 g_xv[ELEMS];
__device__ f16 g_xg[ELEMS];
__device__ f16 g_y[ELEMS];
__device__ float g_r[ELEMS];
__device__ float g_k[ELEMS];
__device__ float g_v[ELEMS];
__device__ float g_g[ELEMS];
__device__ float g_ao[ELEMS];
__device__ f16 g_WrT[CC*CC];
__device__ f16 g_WkT[CC*CC];
__device__ f16 g_WvT[CC*CC];
__device__ f16 g_WgT[CC*CC];
__device__ f16 g_WoT[CC*CC];
__device__ float g_Sc[(size_t)NCHUNK*128*HS*HS];
__device__ float g_S0c[(size_t)NCHUNK*128*HS*HS];

// ---------------------------------------------------------------------------
// helpers
// ---------------------------------------------------------------------------
__device__ __forceinline__ uint32_t smem_u32(const void* p) {
    uint32_t a;
    asm("{ .reg .u64 t; cvta.to.shared.u64 t, %1; cvt.u32.u64 %0, t; }" : "=r"(a) : "l"(p));
    return a;
}
__device__ __forceinline__ void cpa16(uint32_t dst, const void* src) {
    asm volatile("cp.async.cg.shared.global [%0], [%1], 16;" :: "r"(dst), "l"(src));
}
__device__ __forceinline__ void cpa4(uint32_t dst, const void* src) {
    asm volatile("cp.async.ca.shared.global [%0], [%1], 4;" :: "r"(dst), "l"(src));
}
__device__ __forceinline__ void cp_commit() {
    asm volatile("cp.async.commit_group;" ::: "memory");
}
template<int N> __device__ __forceinline__ void cp_wait() {
    asm volatile("cp.async.wait_group %0;" :: "n"(N) : "memory");
}
__device__ __forceinline__ void ldsm4(uint32_t (&r)[4], uint32_t addr) {
    asm volatile("ldmatrix.sync.aligned.m8n8.x4.shared.b16 {%0,%1,%2,%3}, [%4];"
                 : "=r"(r[0]), "=r"(r[1]), "=r"(r[2]), "=r"(r[3]) : "r"(addr));
}
__device__ __forceinline__ void mma_f16(float (&c)[4], const uint32_t (&a)[4],
                                        uint32_t b0, uint32_t b1) {
    asm volatile(
        "mma.sync.aligned.m16n8k16.row.col.f32.f16.f16.f32 "
        "{%0,%1,%2,%3}, {%4,%5,%6,%7}, {%8,%9}, {%0,%1,%2,%3};"
        : "+f"(c[0]), "+f"(c[1]), "+f"(c[2]), "+f"(c[3])
        : "r"(a[0]), "r"(a[1]), "r"(a[2]), "r"(a[3]), "r"(b0), "r"(b1));
}
__device__ __forceinline__ uint32_t pack_h2(float a, float b) {
    __half2 h = __floats2half2_rn(a, b);
    return *(uint32_t*)&h;
}
// ---- packed f32x2 (sm_100 family) ----
__device__ __forceinline__ uint64_t pk2(float x) {
    uint64_t r; asm("mov.b64 %0, {%1, %1};" : "=l"(r) : "f"(x)); return r;
}
__device__ __forceinline__ uint64_t pk2b(float lo, float hi) {
    uint64_t r; asm("mov.b64 %0, {%1, %2};" : "=l"(r) : "f"(lo), "f"(hi)); return r;
}
__device__ __forceinline__ void unpk2(uint64_t p, float& lo, float& hi) {
    asm("mov.b64 {%0, %1}, %2;" : "=f"(lo), "=f"(hi) : "l"(p));
}
__device__ __forceinline__ uint64_t mul2(uint64_t a, uint64_t b) {
    uint64_t r; asm("mul.rn.f32x2 %0, %1, %2;" : "=l"(r) : "l"(a), "l"(b)); return r;
}
__device__ __forceinline__ uint64_t fma2(uint64_t a, uint64_t b, uint64_t c) {
    uint64_t r; asm("fma.rn.f32x2 %0, %1, %2, %3;" : "=l"(r) : "l"(a), "l"(b), "l"(c)); return r;
}

// ---------------------------------------------------------------------------
// 1) Token-shift mixing -> fp16 planes
// ---------------------------------------------------------------------------
__global__ void mix_kernel(const float* __restrict__ x,
                           const float* __restrict__ tmk, const float* __restrict__ tmv,
                           const float* __restrict__ tmr, const float* __restrict__ tmg,
                           f16* __restrict__ xk, f16* __restrict__ xv,
                           f16* __restrict__ xr, f16* __restrict__ xg) {
    size_t i4 = (size_t)blockIdx.x * blockDim.x + threadIdx.x;
    if (i4 >= ELEMS / 4) return;
    size_t idx = i4 * 4;
    int c = (int)(idx % CC);
    int t = (int)((idx / CC) % TTOT);

    float4 xc = *(const float4*)(x + idx);
    float4 xp = make_float4(0.f, 0.f, 0.f, 0.f);
    if (t != 0) xp = *(const float4*)(x + idx - CC);
    float4 mk = *(const float4*)(tmk + c);
    float4 mv = *(const float4*)(tmv + c);
    float4 mr = *(const float4*)(tmr + c);
    float4 mg = *(const float4*)(tmg + c);

    uint2 o;
    o.x = pack_h2(xc.x * mk.x + xp.x * (1.f - mk.x), xc.y * mk.y + xp.y * (1.f - mk.y));
    o.y = pack_h2(xc.z * mk.z + xp.z * (1.f - mk.z), xc.w * mk.w + xp.w * (1.f - mk.w));
    *(uint2*)(xk + idx) = o;
    o.x = pack_h2(xc.x * mv.x + xp.x * (1.f - mv.x), xc.y * mv.y + xp.y * (1.f - mv.y));
    o.y = pack_h2(xc.z * mv.z + xp.z * (1.f - mv.z), xc.w * mv.w + xp.w * (1.f - mv.w));
    *(uint2*)(xv + idx) = o;
    o.x = pack_h2(xc.x * mr.x + xp.x * (1.f - mr.x), xc.y * mr.y + xp.y * (1.f - mr.y));
    o.y = pack_h2(xc.z * mr.z + xp.z * (1.f - mr.z), xc.w * mr.w + xp.w * (1.f - mr.w));
    *(uint2*)(xr + idx) = o;
    o.x = pack_h2(xc.x * mg.x + xp.x * (1.f - mg.x), xc.y * mg.y + xp.y * (1.f - mg.y));
    o.y = pack_h2(xc.z * mg.z + xp.z * (1.f - mg.z), xc.w * mg.w + xp.w * (1.f - mg.w));
    *(uint2*)(xg + idx) = o;
}

// ---------------------------------------------------------------------------
// 2) Weight prep (batched over grid.z)
// ---------------------------------------------------------------------------
struct WB { const float* W[5]; f16* O[5]; };

__global__ void wprep_b(WB wb) {
    const float* __restrict__ W = wb.W[blockIdx.z];
    f16* __restrict__ WT = wb.O[blockIdx.z];
    __shared__ float t[32][33];
    int n0 = blockIdx.x * 32, k0 = blockIdx.y * 32;
    int tx = threadIdx.x, ty = threadIdx.y;
    #pragma unroll
    for (int r = ty; r < 32; r += 8)
        t[r][tx] = W[(size_t)(k0 + r) * CC + n0 + tx];
    __syncthreads();
    #pragma unroll
    for (int r = ty; r < 32; r += 8)
        WT[(size_t)(n0 + r) * CC + k0 + tx] = __float2half_rn(t[tx][r]);
}

// ---------------------------------------------------------------------------
// 3) Batched fp16 GEMM — R11 schedule (frozen local optimum)
// ---------------------------------------------------------------------------
struct GB {
    const f16* Ap[4]; const f16* Bp[4];
    float* Cp[4]; int act[4];
};

__global__ __launch_bounds__(256, 2) void tc_gemm_b(GB gb) {
    int z = blockIdx.z;
    const f16* __restrict__ A = gb.Ap[z];
    const f16* __restrict__ B = gb.Bp[z];
    float* __restrict__ C = gb.Cp[z];
    int act = gb.act[z];

    extern __shared__ char smem[];
    uint32_t sb = smem_u32(smem);

    int tid = threadIdx.x;
    int lane = tid & 31;
    int wm = (tid >> 5) & 3;
    int wn = tid >> 7;
    int mBase = blockIdx.y * BM;
    int nBase = blockIdx.x * BN;

    uint32_t dA = (uint32_t)((tid >> 2) * 80 + (tid & 3) * 16);
    const f16* pA = A + (size_t)(mBase + (tid >> 2)) * CC + (tid & 3) * 8;
    const f16* pB = B + (size_t)(nBase + (tid >> 2)) * CC + (tid & 3) * 8;

    float acc[2][8][4];
    #pragma unroll
    for (int i = 0; i < 2; i++)
        #pragma unroll
        for (int j = 0; j < 8; j++)
            #pragma unroll
            for (int q = 0; q < 4; q++) acc[i][j][q] = 0.0f;

    #pragma unroll
    for (int s = 0; s < NSTG - 1; s++) {
        uint32_t stb = sb + s * STAGE_B;
        int k0 = s * BKT;
        cpa16(stb + dA,                 pA + k0);
        cpa16(stb + dA + 5120,          pA + 64 * CC + k0);
        cpa16(stb + TILE_B + dA,        pB + k0);
        cpa16(stb + TILE_B + dA + 5120, pB + 64 * CC + k0);
        cp_commit();
    }

    uint32_t aRow = (uint32_t)(wm * 32 + ((lane >> 3) & 1) * 8 + (lane & 7));
    uint32_t aCol = (uint32_t)((lane >> 4) * 16);
    uint32_t bRow = (uint32_t)(wn * 64 + (lane >> 4) * 8 + (lane & 7));
    uint32_t bCol = (uint32_t)(((lane >> 3) & 1) * 16);
    int ksSkew = wm & 1;

    for (int kt = 0; kt < KTILES; kt++) {
        cp_wait<NSTG - 2>();
        __syncthreads();

        int nt = kt + NSTG - 1;
        if (nt < KTILES) {
            uint32_t stb = sb + (nt & (NSTG - 1)) * STAGE_B;
            int k0 = nt * BKT;
            cpa16(stb + dA,                 pA + k0);
            cpa16(stb + dA + 5120,          pA + 64 * CC + k0);
            cpa16(stb + TILE_B + dA,        pB + k0);
            cpa16(stb + TILE_B + dA + 5120, pB + 64 * CC + k0);
        }
        cp_commit();

        uint32_t stg = sb + (kt & (NSTG - 1)) * STAGE_B;

        #pragma unroll
        for (int kss = 0; kss < 2; kss++) {
            int ks = kss ^ ksSkew;
            uint32_t a_f[2][4];
            #pragma unroll
            for (int mi = 0; mi < 2; mi++) {
                uint32_t ra = (aRow + mi * 16) * 80 + aCol + ks * 32;
                ldsm4(a_f[mi], stg + ra);
            }
            #pragma unroll
            for (int bp = 0; bp < 2; bp++) {
                uint32_t b0[4], b1[4];
                {
                    uint32_t rb0 = (bRow + (2*bp + 0) * 16) * 80 + bCol + ks * 32;
                    uint32_t rb1 = (bRow + (2*bp + 1) * 16) * 80 + bCol + ks * 32;
                    ldsm4(b0, stg + TILE_B + rb0);
                    ldsm4(b1, stg + TILE_B + rb1);
                }
                #pragma unroll
                for (int mi = 0; mi < 2; mi++) {
                    mma_f16(acc[mi][4*bp + 0], a_f[mi], b0[0], b0[1]);
                    mma_f16(acc[mi][4*bp + 1], a_f[mi], b0[2], b0[3]);
                    mma_f16(acc[mi][4*bp + 2], a_f[mi], b1[0], b1[1]);
                    mma_f16(acc[mi][4*bp + 3], a_f[mi], b1[2], b1[3]);
                }
            }
        }
    }

    int mrow = mBase + wm * 32 + (lane >> 2);
    int ncolbase = nBase + wn * 64 + (lane & 3) * 2;
    #pragma unroll
    for (int mi = 0; mi < 2; mi++) {
        #pragma unroll
        for (int bp = 0; bp < 2; bp++) {
            #pragma unroll
            for (int s = 0; s < 4; s++) {
                int njp = 2*bp + (s >> 1);
                int q = s & 1;
                int ni_col = njp * 16 + q * 8;
                float v0 = acc[mi][4*bp + s][0], v1 = acc[mi][4*bp + s][1];
                float v2 = acc[mi][4*bp + s][2], v3 = acc[mi][4*bp + s][3];
                if (act) {
                    v0 = v0 / (1.0f + expf(-v0));
                    v1 = v1 / (1.0f + expf(-v1));
                    v2 = v2 / (1.0f + expf(-v2));
                    v3 = v3 / (1.0f + expf(-v3));
                }
                float* p0 = C + (size_t)(mrow + mi * 16) * CC + ncolbase + ni_col;
                float* p1 = p0 + 8 * CC;
                *(float2*)p0 = make_float2(v0, v1);
                *(float2*)p1 = make_float2(v2, v3);
            }
        }
    }
}

// ---------------------------------------------------------------------------
// 4) Chunked RWKV scan — f32x2 math, cp.async double-buffer prefetch
// ---------------------------------------------------------------------------
__global__ __launch_bounds__(HS) void scanA_kernel(
        const float* __restrict__ k, const float* __restrict__ v,
        const float* __restrict__ td, float* __restrict__ Sc) {
    int bh = blockIdx.x;
    int chunk = blockIdx.y;
    int b = bh >> 5, h = bh & 31;
    int j = threadIdx.x;

    float w = expf(-expf(td[h]));
    uint64_t w2 = pk2(w);
    uint64_t S2[32];
    #pragma unroll
    for (int p = 0; p < 32; p++) S2[p] = 0ull;

    __shared__ __align__(16) float sk[8][HS], sv[8][HS];
    uint32_t skb = smem_u32(sk), svb = smem_u32(sv);
    size_t base = (size_t)b * TTOT * CC + (size_t)h * HS;
    int t0 = chunk * TCH;

    #pragma unroll
    for (int q = 0; q < 4; q++) {
        size_t o0 = base + (size_t)(t0 + q) * CC + j;
        cpa4(skb + (uint32_t)((q * HS + j) * 4), k + o0);
        cpa4(svb + (uint32_t)((q * HS + j) * 4), v + o0);
    }
    cp_commit();
    cp_wait<0>();
    __syncthreads();

    for (int i = 0; i < TCH; i += 4) {
        int pb = (i >> 2) & 1;
        int cb = pb * 4;
        int qb = (pb ^ 1) * 4;
        if (i + 4 < TCH) {
            #pragma unroll
            for (int q = 0; q < 4; q++) {
                size_t o2 = base + (size_t)(t0 + i + 4 + q) * CC + j;
                cpa4(skb + (uint32_t)(((qb + q) * HS + j) * 4), k + o2);
                cpa4(svb + (uint32_t)(((qb + q) * HS + j) * 4), v + o2);
            }
        }
        cp_commit();

        uint64_t vv0 = pk2(sv[cb][j]),   vv1 = pk2(sv[cb+1][j]);
        uint64_t vv2 = pk2(sv[cb+2][j]), vv3 = pk2(sv[cb+3][j]);
        const uint64_t* k0r = (const uint64_t*)sk[cb];
        const uint64_t* k1r = (const uint64_t*)sk[cb+1];
        const uint64_t* k2r = (const uint64_t*)sk[cb+2];
        const uint64_t* k3r = (const uint64_t*)sk[cb+3];
        #pragma unroll
        for (int p = 0; p < 32; p++) {
            uint64_t s2 = S2[p];
            s2 = fma2(w2, s2, mul2(k0r[p], vv0));
            s2 = fma2(w2, s2, mul2(k1r[p], vv1));
            s2 = fma2(w2, s2, mul2(k2r[p], vv2));
            S2[p] = fma2(w2, s2, mul2(k3r[p], vv3));
        }
        cp_wait<0>();
        __syncthreads();
    }
    size_t o = ((size_t)(chunk * 128 + bh) * HS) * HS + j;
    #pragma unroll
    for (int p = 0; p < 32; p++) {
        float lo, hi;
        unpk2(S2[p], lo, hi);
        Sc[o + (size_t)(2*p)   * HS] = lo;
        Sc[o + (size_t)(2*p+1) * HS] = hi;
    }
}

// elementwise-parallel inter-chunk combine: each thread owns one (bh,a,j)
__global__ __launch_bounds__(256) void scanB_kernel(
        const float* __restrict__ s0, const float* __restrict__ Sc,
        const float* __restrict__ td, float* __restrict__ S0c) {
    size_t e = (size_t)blockIdx.x * 256 + threadIdx.x;   // 0..524287
    int h = (int)((e >> 12) & 31);
    float wT = expf(-expf(td[h]) * (float)TCH);

    float s = s0[e];
    #pragma unroll 4
    for (int c = 0; c < NCHUNK; c++) {
        size_t o = (size_t)c * (128 * HS * HS) + e;
        S0c[o] = s;
        s = fmaf(wT, s, Sc[o]);
    }
}

__global__ __launch_bounds__(HS) void scanC_kernel(
        const float* __restrict__ r, const float* __restrict__ k,
        const float* __restrict__ v, const float* __restrict__ td,
        const float* __restrict__ tf, const float* __restrict__ S0c,
        float* __restrict__ out) {
    int bh = blockIdx.x;
    int chunk = blockIdx.y;
    int b = bh >> 5, h = bh & 31;
    int j = threadIdx.x;

    float w = expf(-expf(td[h]));
    float u = tf[h];
    uint64_t w2 = pk2(w);

    uint64_t S2[32];
    size_t so = ((size_t)(chunk * 128 + bh) * HS) * HS + j;
    #pragma unroll
    for (int p = 0; p < 32; p++) {
        float lo = S0c[so + (size_t)(2*p)   * HS];
        float hi = S0c[so + (size_t)(2*p+1) * HS];
        S2[p] = pk2b(lo, hi);
    }

    __shared__ __align__(16) float sr[8][HS], sk[8][HS], sv[8][HS];
    uint32_t srb = smem_u32(sr), skb = smem_u32(sk), svb = smem_u32(sv);
    size_t base = (size_t)b * TTOT * CC + (size_t)h * HS;
    int t0 = chunk * TCH;

    #pragma unroll
    for (int q = 0; q < 4; q++) {
        size_t o0 = base + (size_t)(t0 + q) * CC + j;
        cpa4(srb + (uint32_t)((q * HS + j) * 4), r + o0);
        cpa4(skb + (uint32_t)((q * HS + j) * 4), k + o0);
        cpa4(svb + (uint32_t)((q * HS + j) * 4), v + o0);
    }
    cp_commit();
    cp_wait<0>();
    __syncthreads();

    for (int i = 0; i < TCH; i += 4) {
        int pb = (i >> 2) & 1;
        int cb = pb * 4;
        int qb = (pb ^ 1) * 4;
        if (i + 4 < TCH) {
            #pragma unroll
            for (int q = 0; q < 4; q++) {
                size_t o2 = base + (size_t)(t0 + i + 4 + q) * CC + j;
                cpa4(srb + (uint32_t)(((qb + q) * HS + j) * 4), r + o2);
                cpa4(skb + (uint32_t)(((qb + q) * HS + j) * 4), k + o2);
                cpa4(svb + (uint32_t)(((qb + q) * HS + j) * 4), v + o2);
            }
        }
        cp_commit();

        float vj0 = sv[cb][j],   vj1 = sv[cb+1][j];
        float vj2 = sv[cb+2][j], vj3 = sv[cb+3][j];
        uint64_t vv0 = pk2(vj0), vv1 = pk2(vj1), vv2 = pk2(vj2), vv3 = pk2(vj3);
        const uint64_t* r0r = (const uint64_t*)sr[cb];
        const uint64_t* r1r = (const uint64_t*)sr[cb+1];
        const uint64_t* r2r = (const uint64_t*)sr[cb+2];
        const uint64_t* r3r = (const uint64_t*)sr[cb+3];
        const uint64_t* k0r = (const uint64_t*)sk[cb];
        const uint64_t* k1r = (const uint64_t*)sk[cb+1];
        const uint64_t* k2r = (const uint64_t*)sk[cb+2];
        const uint64_t* k3r = (const uint64_t*)sk[cb+3];
        uint64_t kr0 = 0ull, o0 = 0ull, kr1 = 0ull, o1 = 0ull;
        uint64_t kr2 = 0ull, o2 = 0ull, kr3 = 0ull, o3 = 0ull;
        #pragma unroll
        for (int p = 0; p < 32; p++) {
            uint64_t sa = S2[p];
            uint64_t r0 = r0r[p], k0 = k0r[p];
            kr0 = fma2(r0, k0, kr0);
            o0  = fma2(r0, sa, o0);
            sa  = fma2(w2, sa, mul2(k0, vv0));
            uint64_t r1 = r1r[p], k1 = k1r[p];
            kr1 = fma2(r1, k1, kr1);
            o1  = fma2(r1, sa, o1);
            sa  = fma2(w2, sa, mul2(k1, vv1));
            uint64_t r2 = r2r[p], k2 = k2r[p];
            kr2 = fma2(r2, k2, kr2);
            o2  = fma2(r2, sa, o2);
            sa  = fma2(w2, sa, mul2(k2, vv2));
            uint64_t r3 = r3r[p], k3 = k3r[p];
            kr3 = fma2(r3, k3, kr3);
            o3  = fma2(r3, sa, o3);
            S2[p] = fma2(w2, sa, mul2(k3, vv3));
        }
        float lo, hi;
        float kr0f, o0f, kr1f, o1f, kr2f, o2f, kr3f, o3f;
        unpk2(kr0, lo, hi); kr0f = lo + hi;
        unpk2(o0,  lo, hi); o0f  = lo + hi;
        unpk2(kr1, lo, hi); kr1f = lo + hi;
        unpk2(o1,  lo, hi); o1f  = lo + hi;
        unpk2(kr2, lo, hi); kr2f = lo + hi;
        unpk2(o2,  lo, hi); o2f  = lo + hi;
        unpk2(kr3, lo, hi); kr3f = lo + hi;
        unpk2(o3,  lo, hi); o3f  = lo + hi;

        size_t ocur = base + (size_t)(t0 + i) * CC;
        out[ocur + j]        = fmaf(u * kr0f, vj0, o0f);
        out[ocur + CC + j]   = fmaf(u * kr1f, vj1, o1f);
        out[ocur + 2*CC + j] = fmaf(u * kr2f, vj2, o2f);
        out[ocur + 3*CC + j] = fmaf(u * kr3f, vj3, o3f);

        cp_wait<0>();
        __syncthreads();
    }
}

// ---------------------------------------------------------------------------
// 5) GroupNorm * gamma + beta, * g -> fp16 y
// ---------------------------------------------------------------------------
__global__ void gn_mul_kernel(const float* __restrict__ x, const float* __restrict__ g,
                              const float* __restrict__ gamma, const float* __restrict__ beta,
                              f16* __restrict__ y) {
    int warp = (int)((blockIdx.x * blockDim.x + threadIdx.x) >> 5);
    int lane = threadIdx.x & 31;
    if (warp >= ROWS * NH) return;
    int row = warp >> 5;
    int h   = warp & 31;
    size_t base = (size_t)row * CC + (size_t)h * HS;

    float x0 = x[base + lane]      * 0.125f;
    float x1 = x[base + lane + 32] * 0.125f;
    float sum = x0 + x1;
    float sq  = fmaf(x0, x0, x1 * x1);
    #pragma unroll
    for (int o = 16; o; o >>= 1) {
        sum += __shfl_xor_sync(0xffffffffu, sum, o);
        sq  += __shfl_xor_sync(0xffffffffu, sq,  o);
    }
    float mu  = sum * (1.0f / 64.0f);
    float var = sq  * (1.0f / 64.0f) - mu * mu;
    float inv = rsqrtf(var + 1e-5f);

    int c0 = h * HS + lane, c1 = c0 + 32;
    float y0 = ((x0 - mu) * inv * gamma[c0] + beta[c0]) * g[base + lane];
    float y1 = ((x1 - mu) * inv * gamma[c1] + beta[c1]) * g[base + lane + 32];
    y[base + lane]      = __float2half_rn(y0);
    y[base + lane + 32] = __float2half_rn(y1);
}

// ---------------------------------------------------------------------------
// Launcher
// ---------------------------------------------------------------------------
extern "C" void kernel_launch(void* const* d_in, const int* in_sizes, int n_in,
                              void* d_out, int out_size) {
    const float* x     = (const float*)d_in[0];
    const float* Wr    = (const float*)d_in[1];
    const float* Wk    = (const float*)d_in[2];
    const float* Wv    = (const float*)d_in[3];
    const float* Wg    = (const float*)d_in[4];
    const float* Wo    = (const float*)d_in[5];
    const float* gamma = (const float*)d_in[6];
    const float* beta  = (const float*)d_in[7];
    const float* tmk   = (const float*)d_in[8];
    const float* tmv   = (const float*)d_in[9];
    const float* tmr   = (const float*)d_in[10];
    const float* tmg   = (const float*)d_in[11];
    const float* td    = (const float*)d_in[12];
    const float* tf    = (const float*)d_in[13];
    const float* s0    = (const float*)d_in[14];
    float* out = (float*)d_out;

    static bool attr_done = false;
    if (!attr_done) {
        cudaFuncSetAttribute(tc_gemm_b, cudaFuncAttributeMaxDynamicSharedMemorySize, SMEM_B);
        attr_done = true;
    }

    f16 *xr,*xk,*xv,*xg,*yb;
    f16 *wrt,*wkt,*wvt,*wgt,*wot;
    float *rb,*kb,*vb,*gb,*ao,*Sc,*S0c;
    cudaGetSymbolAddress((void**)&xr, g_xr);
    cudaGetSymbolAddress((void**)&xk, g_xk);
    cudaGetSymbolAddress((void**)&xv, g_xv);
    cudaGetSymbolAddress((void**)&xg, g_xg);
    cudaGetSymbolAddress((void**)&yb, g_y);
    cudaGetSymbolAddress((void**)&rb, g_r); cudaGetSymbolAddress((void**)&kb, g_k);
    cudaGetSymbolAddress((void**)&vb, g_v); cudaGetSymbolAddress((void**)&gb, g_g);
    cudaGetSymbolAddress((void**)&ao, g_ao);
    cudaGetSymbolAddress((void**)&Sc, g_Sc); cudaGetSymbolAddress((void**)&S0c, g_S0c);
    cudaGetSymbolAddress((void**)&wrt, g_WrT);
    cudaGetSymbolAddress((void**)&wkt, g_WkT);
    cudaGetSymbolAddress((void**)&wvt, g_WvT);
    cudaGetSymbolAddress((void**)&wgt, g_WgT);
    cudaGetSymbolAddress((void**)&wot, g_WoT);

    WB wb;
    wb.W[0] = Wr; wb.W[1] = Wk; wb.W[2] = Wv; wb.W[3] = Wg; wb.W[4] = Wo;
    wb.O[0] = wrt; wb.O[1] = wkt; wb.O[2] = wvt; wb.O[3] = wgt; wb.O[4] = wot;
    wprep_b<<<dim3(CC/32, CC/32, 5), dim3(32, 8)>>>(wb);

    int mixBlocks = (int)((ELEMS / 4 + 255) / 256);
    mix_kernel<<<mixBlocks, 256>>>(x, tmk, tmv, tmr, tmg, xk, xv, xr, xg);

    GB g4;
    g4.Ap[0] = xr; g4.Bp[0] = wrt; g4.Cp[0] = rb; g4.act[0] = 0;
    g4.Ap[1] = xk; g4.Bp[1] = wkt; g4.Cp[1] = kb; g4.act[1] = 0;
    g4.Ap[2] = xv; g4.Bp[2] = wvt; g4.Cp[2] = vb; g4.act[2] = 0;
    g4.Ap[3] = xg; g4.Bp[3] = wgt; g4.Cp[3] = gb; g4.act[3] = 1;
    tc_gemm_b<<<dim3(CC/BN, ROWS/BM, 4), 256, SMEM_B>>>(g4);

    dim3 sg(128, NCHUNK);
    scanA_kernel<<<sg, HS>>>(kb, vb, td, Sc);
    scanB_kernel<<<(128 * HS * HS) / 256, 256>>>(s0, Sc, td, S0c);
    scanC_kernel<<<sg, HS>>>(rb, kb, vb, td, tf, S0c, ao);

    gn_mul_kernel<<<(ROWS * NH) / 8, 256>>>(ao, gb, gamma, beta, yb);

    GB g1;
    g1.Ap[0] = yb; g1.Bp[0] = wot; g1.Cp[0] = out; g1.act[0] = 0;
    g1.Ap[1] = yb; g1.Bp[1] = wot; g1.Cp[1] = out; g1.act[1] = 0;
    g1.Ap[2] = yb; g1.Bp[2] = wot; g1.Cp[2] = out; g1.act[2] = 0;
    g1.Ap[3] = yb; g1.Bp[3] = wot; g1.Cp[3] = out; g1.act[3] = 0;
    tc_gemm_b<<<dim3(CC/BN, ROWS/BM, 1), 256, SMEM_B>>>(g1);
}